// round 1
// baseline (speedup 1.0000x reference)
#include <cuda_runtime.h>
#include <cstdint>

// ---------------------------------------------------------------------------
// Problem constants
// ---------------------------------------------------------------------------
#define B_   8
#define C_   256
#define N_   4096          // 64*64 spatial tokens
#define G_   8             // groups
#define CPG_ 32            // channels per group
#define EPS_ 1e-5f
#define SCALE_ 0.0625f     // 1/sqrt(256)

// ---------------------------------------------------------------------------
// Device scratch (no cudaMalloc allowed)
// ---------------------------------------------------------------------------
__device__ float g_qkv[(size_t)B_ * 3 * C_ * N_];   // (B, 768, N): q=[0,256), k=[256,512), v=[512,768)
__device__ float g_attn[(size_t)B_ * C_ * N_];      // (B, C, N) attention output
__device__ float g_fs[B_ * C_];                     // fused GN scale per (b,c)
__device__ float g_fb[B_ * C_];                     // fused GN bias  per (b,c)

// ---------------------------------------------------------------------------
// Kernel 1: GroupNorm stats -> fused per-channel scale/bias
//   xn[b,c,n] = x[b,c,n] * fs[b,c] + fb[b,c]
// ---------------------------------------------------------------------------
__global__ __launch_bounds__(256) void gn_stats_kernel(
    const float* __restrict__ x,
    const float* __restrict__ gamma,
    const float* __restrict__ beta)
{
    int b = blockIdx.x >> 3;
    int g = blockIdx.x & 7;
    const float4* p = reinterpret_cast<const float4*>(
        x + ((size_t)(b * C_ + g * CPG_)) * N_);
    // 32 channels * 4096 = 131072 floats = 32768 float4
    float s1 = 0.f, s2 = 0.f;
    for (int i = threadIdx.x; i < 32768; i += 256) {
        float4 v = p[i];
        s1 += (v.x + v.y) + (v.z + v.w);
        s2 += (v.x * v.x + v.y * v.y) + (v.z * v.z + v.w * v.w);
    }
    #pragma unroll
    for (int off = 16; off; off >>= 1) {
        s1 += __shfl_xor_sync(0xffffffffu, s1, off);
        s2 += __shfl_xor_sync(0xffffffffu, s2, off);
    }
    __shared__ float a1[8], a2[8];
    __shared__ float sh_mean, sh_rstd;
    int warp = threadIdx.x >> 5;
    if ((threadIdx.x & 31) == 0) { a1[warp] = s1; a2[warp] = s2; }
    __syncthreads();
    if (threadIdx.x == 0) {
        float t1 = 0.f, t2 = 0.f;
        #pragma unroll
        for (int w = 0; w < 8; w++) { t1 += a1[w]; t2 += a2[w]; }
        float mean = t1 * (1.f / 131072.f);
        float var  = t2 * (1.f / 131072.f) - mean * mean;
        sh_mean = mean;
        sh_rstd = rsqrtf(var + EPS_);
    }
    __syncthreads();
    if (threadIdx.x < CPG_) {
        int c  = g * CPG_ + threadIdx.x;
        float ga = gamma[c];
        float fs = sh_rstd * ga;
        g_fs[b * C_ + c] = fs;
        g_fb[b * C_ + c] = beta[c] - sh_mean * fs;
    }
}

// ---------------------------------------------------------------------------
// Kernel 2: QKV GEMM with fused GroupNorm normalize.
//   qkv[b,o,n] = sum_c w[o,c] * xn[b,c,n] + bias[o]
// Tile: 64 (o) x 64 (n), BK=16, 256 threads, 4x4 microtile.
// ---------------------------------------------------------------------------
__global__ __launch_bounds__(256) void qkv_gemm_kernel(
    const float* __restrict__ x,
    const float* __restrict__ w,
    const float* __restrict__ bias)
{
    __shared__ float Ws[16][65];   // [c_local][o_local], padded: conflict-free fill
    __shared__ float Xs[16][64];   // [c_local][n_local]
    int n0 = blockIdx.x * 64;
    int o0 = blockIdx.y * 64;
    int b  = blockIdx.z;
    int tid = threadIdx.x;
    int tx = tid & 15, ty = tid >> 4;
    const float* xb  = x + (size_t)b * C_ * N_;
    const float* fsb = g_fs + b * C_;
    const float* fbb = g_fb + b * C_;
    float acc[4][4] = {};
    int wc = tid & 15, wo = tid >> 4;   // W fill coords
    int xn = tid & 63, xc = tid >> 6;   // X fill coords

    for (int cb = 0; cb < C_; cb += 16) {
        #pragma unroll
        for (int oo = 0; oo < 64; oo += 16)
            Ws[wc][wo + oo] = w[(size_t)(o0 + wo + oo) * C_ + cb + wc];
        #pragma unroll
        for (int cc = 0; cc < 16; cc += 4) {
            int c = cb + xc + cc;
            Xs[xc + cc][xn] = xb[(size_t)c * N_ + n0 + xn] * fsb[c] + fbb[c];
        }
        __syncthreads();
        #pragma unroll
        for (int kk = 0; kk < 16; kk++) {
            float4 xv = *(const float4*)&Xs[kk][4 * tx];
            float w0 = Ws[kk][4 * ty + 0];
            float w1 = Ws[kk][4 * ty + 1];
            float w2 = Ws[kk][4 * ty + 2];
            float w3 = Ws[kk][4 * ty + 3];
            acc[0][0] += w0 * xv.x; acc[0][1] += w0 * xv.y; acc[0][2] += w0 * xv.z; acc[0][3] += w0 * xv.w;
            acc[1][0] += w1 * xv.x; acc[1][1] += w1 * xv.y; acc[1][2] += w1 * xv.z; acc[1][3] += w1 * xv.w;
            acc[2][0] += w2 * xv.x; acc[2][1] += w2 * xv.y; acc[2][2] += w2 * xv.z; acc[2][3] += w2 * xv.w;
            acc[3][0] += w3 * xv.x; acc[3][1] += w3 * xv.y; acc[3][2] += w3 * xv.z; acc[3][3] += w3 * xv.w;
        }
        __syncthreads();
    }
    #pragma unroll
    for (int i = 0; i < 4; i++) {
        int o = o0 + 4 * ty + i;
        float bo = bias[o];
        float4 r = make_float4(acc[i][0] + bo, acc[i][1] + bo,
                               acc[i][2] + bo, acc[i][3] + bo);
        *(float4*)&g_qkv[((size_t)b * 768 + o) * N_ + n0 + 4 * tx] = r;
    }
}

// ---------------------------------------------------------------------------
// Kernel 3: flash attention (fp32, online softmax).
// One CTA = 64 query rows of one batch. 64 key blocks of 64.
// smem: Qs[64][257] (pre-scaled), Kt[256][64], Vs[256][65], Ps[64][65]
// ---------------------------------------------------------------------------
#define FLASH_SMEM_FLOATS (64 * 257 + 256 * 64 + 256 * 65 + 64 * 65)
#define FLASH_SMEM_BYTES  (FLASH_SMEM_FLOATS * 4)

__global__ __launch_bounds__(256, 1) void flash_kernel()
{
    extern __shared__ float sm[];
    float* Qs = sm;                       // [64][257]
    float* Kt = sm + 64 * 257;            // [256][64]  (kk-major)
    float* Vs = Kt + 256 * 64;            // [256][65]  ([c][k], padded)
    float* Ps = Vs + 256 * 65;            // [64][65]

    int b  = blockIdx.y;
    int n0 = blockIdx.x * 64;
    int tid = threadIdx.x;
    int tx = tid & 15, ty = tid >> 4;

    const float* qg = g_qkv + (size_t)b * 768 * N_;
    const float* kg = qg + (size_t)C_ * N_;
    const float* vg = qg + (size_t)2 * C_ * N_;

    // Load Q block (transposed to [n][c]) with pre-applied 1/sqrt(C) scale.
    {
        int n_l = tid & 63, c0 = tid >> 6;
        for (int c = c0; c < C_; c += 4)
            Qs[n_l * 257 + c] = qg[(size_t)c * N_ + n0 + n_l] * SCALE_;
    }

    float m_i[4] = { -1e30f, -1e30f, -1e30f, -1e30f };
    float l_i[4] = {};
    float O[4][16] = {};

    for (int kb = 0; kb < 64; kb++) {
        __syncthreads();   // prev-iter consumers done (and Q fill on iter 0)
        // Fill Kt[kk][k_l] from kg[kk][kb*64 + k_l]  (coalesced, conflict-free)
        for (int idx = tid; idx < 4096; idx += 256) {
            int kk = idx >> 4, c4 = (idx & 15) * 4;
            *(float4*)&Kt[kk * 64 + c4] =
                *(const float4*)&kg[(size_t)kk * N_ + kb * 64 + c4];
        }
        // Fill Vs[c][k] from vg[c][kb*64 + k]
        for (int idx = tid; idx < 16384; idx += 256) {
            int c = idx >> 6, k = idx & 63;
            Vs[c * 65 + k] = vg[(size_t)c * N_ + kb * 64 + k];
        }
        __syncthreads();

        // S = Q * K^T  (rows 4ty+i, keys 4tx+j)
        float s[4][4] = {};
        #pragma unroll 4
        for (int kk = 0; kk < 256; kk++) {
            float4 kv = *(const float4*)&Kt[kk * 64 + 4 * tx];
            float q0 = Qs[(4 * ty + 0) * 257 + kk];
            float q1 = Qs[(4 * ty + 1) * 257 + kk];
            float q2 = Qs[(4 * ty + 2) * 257 + kk];
            float q3 = Qs[(4 * ty + 3) * 257 + kk];
            s[0][0] += q0 * kv.x; s[0][1] += q0 * kv.y; s[0][2] += q0 * kv.z; s[0][3] += q0 * kv.w;
            s[1][0] += q1 * kv.x; s[1][1] += q1 * kv.y; s[1][2] += q1 * kv.z; s[1][3] += q1 * kv.w;
            s[2][0] += q2 * kv.x; s[2][1] += q2 * kv.y; s[2][2] += q2 * kv.z; s[2][3] += q2 * kv.w;
            s[3][0] += q3 * kv.x; s[3][1] += q3 * kv.y; s[3][2] += q3 * kv.z; s[3][3] += q3 * kv.w;
        }

        // Online softmax per row; P written to smem.
        #pragma unroll
        for (int i = 0; i < 4; i++) {
            float rmax = fmaxf(fmaxf(s[i][0], s[i][1]), fmaxf(s[i][2], s[i][3]));
            #pragma unroll
            for (int off = 8; off; off >>= 1)
                rmax = fmaxf(rmax, __shfl_xor_sync(0xffffffffu, rmax, off));
            float mnew = fmaxf(m_i[i], rmax);
            float corr = __expf(m_i[i] - mnew);
            float p0 = __expf(s[i][0] - mnew);
            float p1 = __expf(s[i][1] - mnew);
            float p2 = __expf(s[i][2] - mnew);
            float p3 = __expf(s[i][3] - mnew);
            float rs = (p0 + p1) + (p2 + p3);
            #pragma unroll
            for (int off = 8; off; off >>= 1)
                rs += __shfl_xor_sync(0xffffffffu, rs, off);
            l_i[i] = l_i[i] * corr + rs;
            m_i[i] = mnew;
            #pragma unroll
            for (int j = 0; j < 16; j++) O[i][j] *= corr;
            float* pr = &Ps[(4 * ty + i) * 65 + 4 * tx];
            pr[0] = p0; pr[1] = p1; pr[2] = p2; pr[3] = p3;
        }
        __syncthreads();

        // O += P * V   (rows 4ty+i, channels tx+16j)
        #pragma unroll 2
        for (int k = 0; k < 64; k++) {
            float p0 = Ps[(4 * ty + 0) * 65 + k];
            float p1 = Ps[(4 * ty + 1) * 65 + k];
            float p2 = Ps[(4 * ty + 2) * 65 + k];
            float p3 = Ps[(4 * ty + 3) * 65 + k];
            #pragma unroll
            for (int j = 0; j < 16; j++) {
                float v = Vs[(tx + 16 * j) * 65 + k];
                O[0][j] += p0 * v;
                O[1][j] += p1 * v;
                O[2][j] += p2 * v;
                O[3][j] += p3 * v;
            }
        }
    }
    __syncthreads();

    // Normalize and transpose O through smem (reuse Vs) for coalesced store.
    float inv[4];
    #pragma unroll
    for (int i = 0; i < 4; i++) inv[i] = 1.f / l_i[i];
    #pragma unroll
    for (int j = 0; j < 16; j++) {
        int c = tx + 16 * j;
        #pragma unroll
        for (int i = 0; i < 4; i++)
            Vs[c * 65 + 4 * ty + i] = O[i][j] * inv[i];
    }
    __syncthreads();
    {
        int n_l = tid & 63, c0 = tid >> 6;
        for (int c = c0; c < C_; c += 4)
            g_attn[((size_t)b * C_ + c) * N_ + n0 + n_l] = Vs[c * 65 + n_l];
    }
}

// ---------------------------------------------------------------------------
// Kernel 4: output projection + bias + residual.
//   out[b,o,n] = sum_c w_out[o,c]*attn[b,c,n] + b_out[o] + x[b,o,n]
// ---------------------------------------------------------------------------
__global__ __launch_bounds__(256) void out_proj_kernel(
    const float* __restrict__ w,
    const float* __restrict__ bias,
    const float* __restrict__ x,
    float* __restrict__ out)
{
    __shared__ float Ws[16][65];
    __shared__ float Xs[16][64];
    int n0 = blockIdx.x * 64;
    int o0 = blockIdx.y * 64;
    int b  = blockIdx.z;
    int tid = threadIdx.x;
    int tx = tid & 15, ty = tid >> 4;
    const float* ab = g_attn + (size_t)b * C_ * N_;
    float acc[4][4] = {};
    int wc = tid & 15, wo = tid >> 4;
    int xn = tid & 63, xc = tid >> 6;

    for (int cb = 0; cb < C_; cb += 16) {
        #pragma unroll
        for (int oo = 0; oo < 64; oo += 16)
            Ws[wc][wo + oo] = w[(size_t)(o0 + wo + oo) * C_ + cb + wc];
        #pragma unroll
        for (int cc = 0; cc < 16; cc += 4) {
            int c = cb + xc + cc;
            Xs[xc + cc][xn] = ab[(size_t)c * N_ + n0 + xn];
        }
        __syncthreads();
        #pragma unroll
        for (int kk = 0; kk < 16; kk++) {
            float4 xv = *(const float4*)&Xs[kk][4 * tx];
            float w0 = Ws[kk][4 * ty + 0];
            float w1 = Ws[kk][4 * ty + 1];
            float w2 = Ws[kk][4 * ty + 2];
            float w3 = Ws[kk][4 * ty + 3];
            acc[0][0] += w0 * xv.x; acc[0][1] += w0 * xv.y; acc[0][2] += w0 * xv.z; acc[0][3] += w0 * xv.w;
            acc[1][0] += w1 * xv.x; acc[1][1] += w1 * xv.y; acc[1][2] += w1 * xv.z; acc[1][3] += w1 * xv.w;
            acc[2][0] += w2 * xv.x; acc[2][1] += w2 * xv.y; acc[2][2] += w2 * xv.z; acc[2][3] += w2 * xv.w;
            acc[3][0] += w3 * xv.x; acc[3][1] += w3 * xv.y; acc[3][2] += w3 * xv.z; acc[3][3] += w3 * xv.w;
        }
        __syncthreads();
    }
    #pragma unroll
    for (int i = 0; i < 4; i++) {
        int o = o0 + 4 * ty + i;
        float bo = bias[o];
        size_t base = ((size_t)b * C_ + o) * N_ + n0 + 4 * tx;
        float4 res = *(const float4*)&x[base];
        float4 r = make_float4(acc[i][0] + bo + res.x,
                               acc[i][1] + bo + res.y,
                               acc[i][2] + bo + res.z,
                               acc[i][3] + bo + res.w);
        *(float4*)&out[base] = r;
    }
}

// ---------------------------------------------------------------------------
// Launch
// ---------------------------------------------------------------------------
extern "C" void kernel_launch(void* const* d_in, const int* in_sizes, int n_in,
                              void* d_out, int out_size)
{
    const float* x        = (const float*)d_in[0];
    const float* gn_scale = (const float*)d_in[1];
    const float* gn_bias  = (const float*)d_in[2];
    const float* w_qkv    = (const float*)d_in[3];
    const float* b_qkv    = (const float*)d_in[4];
    const float* w_out    = (const float*)d_in[5];
    const float* b_out    = (const float*)d_in[6];
    float* out = (float*)d_out;

    cudaFuncSetAttribute(flash_kernel,
                         cudaFuncAttributeMaxDynamicSharedMemorySize,
                         FLASH_SMEM_BYTES);

    gn_stats_kernel<<<B_ * G_, 256>>>(x, gn_scale, gn_bias);
    qkv_gemm_kernel<<<dim3(N_ / 64, 12, B_), 256>>>(x, w_qkv, b_qkv);
    flash_kernel<<<dim3(N_ / 64, B_), 256, FLASH_SMEM_BYTES>>>();
    out_proj_kernel<<<dim3(N_ / 64, 4, B_), 256>>>(w_out, b_out, x, out);
}

// round 5
// speedup vs baseline: 2.5677x; 2.5677x over previous
#include <cuda_runtime.h>
#include <cstdint>

// ---------------------------------------------------------------------------
// Problem constants
// ---------------------------------------------------------------------------
#define B_   8
#define C_   256
#define N_   4096
#define G_   8
#define CPG_ 32
#define EPS_ 1e-5f
// log2(e) / sqrt(C) folded into Q so P = exp2(S)
#define QSCALE_ 0.09016844270216718f

// ---------------------------------------------------------------------------
// Device scratch
// ---------------------------------------------------------------------------
__device__ float g_q[(size_t)B_ * N_ * C_];     // (B, N, C) token-major
__device__ float g_k[(size_t)B_ * N_ * C_];     // (B, N, C) token-major
__device__ float g_v[(size_t)B_ * N_ * C_];     // (B, N, C) token-major
__device__ float g_attn[(size_t)B_ * C_ * N_];  // (B, C, N) channel-major
__device__ float g_fs[B_ * C_];
__device__ float g_fb[B_ * C_];

// ---------------------------------------------------------------------------
// mma.sync tf32 m16n8k8 (baseline PTX, valid on sm_100 non-'a')
// ---------------------------------------------------------------------------
__device__ __forceinline__ void mma_tf32(float* c,
    uint32_t a0, uint32_t a1, uint32_t a2, uint32_t a3,
    uint32_t b0, uint32_t b1)
{
    asm volatile(
        "mma.sync.aligned.m16n8k8.row.col.f32.tf32.tf32.f32 "
        "{%0,%1,%2,%3}, {%4,%5,%6,%7}, {%8,%9}, {%0,%1,%2,%3};"
        : "+f"(c[0]), "+f"(c[1]), "+f"(c[2]), "+f"(c[3])
        : "r"(a0), "r"(a1), "r"(a2), "r"(a3), "r"(b0), "r"(b1));
}
__device__ __forceinline__ float ex2f(float x) {
    float r;
    asm("ex2.approx.ftz.f32 %0, %1;" : "=f"(r) : "f"(x));
    return r;
}
__device__ __forceinline__ uint32_t f2u(float x) { return __float_as_uint(x); }

// ---------------------------------------------------------------------------
// Kernel 1: GroupNorm stats -> fused per-(b,c) scale/bias
// ---------------------------------------------------------------------------
__global__ __launch_bounds__(256) void gn_stats_kernel(
    const float* __restrict__ x,
    const float* __restrict__ gamma,
    const float* __restrict__ beta)
{
    int b = blockIdx.x >> 3;
    int g = blockIdx.x & 7;
    const float4* p = reinterpret_cast<const float4*>(
        x + ((size_t)(b * C_ + g * CPG_)) * N_);
    float s1 = 0.f, s2 = 0.f;
    for (int i = threadIdx.x; i < 32768; i += 256) {
        float4 v = p[i];
        s1 += (v.x + v.y) + (v.z + v.w);
        s2 += (v.x * v.x + v.y * v.y) + (v.z * v.z + v.w * v.w);
    }
    #pragma unroll
    for (int off = 16; off; off >>= 1) {
        s1 += __shfl_xor_sync(0xffffffffu, s1, off);
        s2 += __shfl_xor_sync(0xffffffffu, s2, off);
    }
    __shared__ float a1[8], a2[8];
    __shared__ float sh_mean, sh_rstd;
    int warp = threadIdx.x >> 5;
    if ((threadIdx.x & 31) == 0) { a1[warp] = s1; a2[warp] = s2; }
    __syncthreads();
    if (threadIdx.x == 0) {
        float t1 = 0.f, t2 = 0.f;
        #pragma unroll
        for (int w = 0; w < 8; w++) { t1 += a1[w]; t2 += a2[w]; }
        float mean = t1 * (1.f / 131072.f);
        float var  = t2 * (1.f / 131072.f) - mean * mean;
        sh_mean = mean;
        sh_rstd = rsqrtf(var + EPS_);
    }
    __syncthreads();
    if (threadIdx.x < CPG_) {
        int c  = g * CPG_ + threadIdx.x;
        float ga = gamma[c];
        float fs = sh_rstd * ga;
        g_fs[b * C_ + c] = fs;
        g_fb[b * C_ + c] = beta[c] - sh_mean * fs;
    }
}

// ---------------------------------------------------------------------------
// Kernel 2: QKV GEMM (fused GN). Q, K, V all written token-major (B, N, C).
// ---------------------------------------------------------------------------
#define TSP 68   // Ts row stride: multiple of 4 -> float4-aligned rows
__global__ __launch_bounds__(256) void qkv_gemm_kernel(
    const float* __restrict__ x,
    const float* __restrict__ w,
    const float* __restrict__ bias)
{
    __shared__ float Ws[16][65];
    __shared__ float Xs[16][64];
    __shared__ float Ts[64][TSP];
    int n0 = blockIdx.x * 64;
    int o0 = blockIdx.y * 64;
    int b  = blockIdx.z;
    int tid = threadIdx.x;
    int tx = tid & 15, ty = tid >> 4;
    const float* xb  = x + (size_t)b * C_ * N_;
    const float* fsb = g_fs + b * C_;
    const float* fbb = g_fb + b * C_;
    float acc[4][4] = {};
    int wc = tid & 15, wo = tid >> 4;
    int xn = tid & 63, xc = tid >> 6;

    for (int cb = 0; cb < C_; cb += 16) {
        #pragma unroll
        for (int oo = 0; oo < 64; oo += 16)
            Ws[wc][wo + oo] = w[(size_t)(o0 + wo + oo) * C_ + cb + wc];
        #pragma unroll
        for (int cc = 0; cc < 16; cc += 4) {
            int c = cb + xc + cc;
            Xs[xc + cc][xn] = xb[(size_t)c * N_ + n0 + xn] * fsb[c] + fbb[c];
        }
        __syncthreads();
        #pragma unroll
        for (int kk = 0; kk < 16; kk++) {
            float4 xv = *(const float4*)&Xs[kk][4 * tx];
            float w0 = Ws[kk][4 * ty + 0];
            float w1 = Ws[kk][4 * ty + 1];
            float w2 = Ws[kk][4 * ty + 2];
            float w3 = Ws[kk][4 * ty + 3];
            acc[0][0] += w0 * xv.x; acc[0][1] += w0 * xv.y; acc[0][2] += w0 * xv.z; acc[0][3] += w0 * xv.w;
            acc[1][0] += w1 * xv.x; acc[1][1] += w1 * xv.y; acc[1][2] += w1 * xv.z; acc[1][3] += w1 * xv.w;
            acc[2][0] += w2 * xv.x; acc[2][1] += w2 * xv.y; acc[2][2] += w2 * xv.z; acc[2][3] += w2 * xv.w;
            acc[3][0] += w3 * xv.x; acc[3][1] += w3 * xv.y; acc[3][2] += w3 * xv.z; acc[3][3] += w3 * xv.w;
        }
        __syncthreads();
    }

    // stage (transpose) then write token-major [n][c]
    int t = o0 >> 8;          // 0 = Q, 1 = K, 2 = V
    #pragma unroll
    for (int i = 0; i < 4; i++) {
        float bo = bias[o0 + 4 * ty + i];
        #pragma unroll
        for (int j = 0; j < 4; j++)
            Ts[4 * tx + j][4 * ty + i] = acc[i][j] + bo;
    }
    __syncthreads();
    float* gdst = (t == 0 ? g_q : (t == 1 ? g_k : g_v)) + (size_t)b * N_ * C_;
    int oo0 = o0 & 255;
    int r = tid >> 2, cq = (tid & 3) * 16;
    float* drow = gdst + (size_t)(n0 + r) * C_ + oo0 + cq;
    #pragma unroll
    for (int v4 = 0; v4 < 4; v4++) {
        float4 val = *(float4*)&Ts[r][cq + 4 * v4];
        *(float4*)(drow + 4 * v4) = val;
    }
}

// ---------------------------------------------------------------------------
// Kernel 3: flash attention on mma.sync tf32.
// 256 threads / 8 warps, warp = 16 query rows -> 128 rows per CTA.
// Key blocks of 32; 128 iterations. No max-subtraction (bounded scores).
// Smem pads chosen for conflict-free fragment LDS:
//   Q pad 260 (==4 mod 32), K pad 260, V pad 264 (==8 mod 32), P pad 36.
// ---------------------------------------------------------------------------
#define QP 260
#define KP 260
#define VP 264
#define PP 36
#define Q_WORDS (128 * QP)              // 33280
#define K_WORDS (32 * KP)               // 8320
#define V_WORDS (32 * VP)               // 8448
#define P_WORDS (128 * PP)              // 4608
#define FL_WORDS (Q_WORDS + K_WORDS + V_WORDS + P_WORDS)
#define FL_SMEM  (FL_WORDS * 4)         // 218624 bytes

__global__ void __launch_bounds__(256, 1) flash_kernel()
{
    extern __shared__ float sm[];
    float* Qs = sm;
    float* Ks = sm + Q_WORDS;
    float* Vs = Ks + K_WORDS;
    float* Ps = Vs + V_WORDS;
    float* Os = sm;                     // epilogue alias (256*129 <= Q_WORDS)

    int tid = threadIdx.x;
    int w   = tid >> 5;
    int lid = tid & 31;
    int g   = lid >> 2;                 // row-in-fragment group 0..7
    int t   = lid & 3;                  // col group 0..3
    int b   = blockIdx.y;
    int n0  = blockIdx.x * 128;
    int wrow = w * 16;                  // warp's base query row (local)

    const float* qg = g_q + ((size_t)b * N_ + n0) * C_;
    const float* kg = g_k + (size_t)b * N_ * C_;
    const float* vg = g_v + (size_t)b * N_ * C_;

    // ---- Q fill: rows 0..127, 256 cols, scaled by log2(e)/sqrt(C)
    for (int idx = tid; idx < 8192; idx += 256) {
        int r = idx >> 6, c4 = idx & 63;
        float4 v = *(const float4*)(qg + (size_t)r * C_ + c4 * 4);
        v.x *= QSCALE_; v.y *= QSCALE_; v.z *= QSCALE_; v.w *= QSCALE_;
        *(float4*)&Qs[r * QP + c4 * 4] = v;
    }

    // Fragment base pointers (conflict-free patterns)
    const float* qa = Qs + (wrow + g) * QP + t;        // A of S-mma
    const float* kb = Ks + g * KP + t;                 // B of S-mma
    const float* pa = Ps + (wrow + g) * PP + t;        // A of PV-mma
    const float* vb = Vs + t * VP + g;                 // B of PV-mma
    float* pw = Ps + (wrow + g) * PP + 2 * t;          // P store row lo

    float Oacc[32][4];
    #pragma unroll
    for (int nb = 0; nb < 32; nb++)
        #pragma unroll
        for (int j = 0; j < 4; j++) Oacc[nb][j] = 0.f;
    float lsum_lo = 0.f, lsum_hi = 0.f;

    for (int i = 0; i < 128; i++) {
        __syncthreads();
        // K tile: 32 keys x 256
        for (int idx = tid; idx < 2048; idx += 256) {
            int r = idx >> 6, c4 = idx & 63;
            *(float4*)&Ks[r * KP + c4 * 4] =
                *(const float4*)(kg + (size_t)(i * 32 + r) * C_ + c4 * 4);
        }
        // V tile: 32 keys x 256
        for (int idx = tid; idx < 2048; idx += 256) {
            int r = idx >> 6, c4 = idx & 63;
            *(float4*)&Vs[r * VP + c4 * 4] =
                *(const float4*)(vg + (size_t)(i * 32 + r) * C_ + c4 * 4);
        }
        __syncthreads();

        // ---- S = Q @ K^T : warp tile 16 x 32, K=256
        float s[4][4];
        #pragma unroll
        for (int nb = 0; nb < 4; nb++)
            #pragma unroll
            for (int j = 0; j < 4; j++) s[nb][j] = 0.f;
        #pragma unroll 4
        for (int k = 0; k < 32; k++) {
            uint32_t a0 = f2u(qa[k * 8]);
            uint32_t a1 = f2u(qa[8 * QP + k * 8]);
            uint32_t a2 = f2u(qa[k * 8 + 4]);
            uint32_t a3 = f2u(qa[8 * QP + k * 8 + 4]);
            #pragma unroll
            for (int nb = 0; nb < 4; nb++) {
                uint32_t b0 = f2u(kb[nb * 8 * KP + k * 8]);
                uint32_t b1 = f2u(kb[nb * 8 * KP + k * 8 + 4]);
                mma_tf32(s[nb], a0, a1, a2, a3, b0, b1);
            }
        }

        // ---- softmax (no max subtraction): P = exp2(S), accumulate row sums
        #pragma unroll
        for (int nb = 0; nb < 4; nb++) {
            float e0 = ex2f(s[nb][0]);
            float e1 = ex2f(s[nb][1]);
            float e2 = ex2f(s[nb][2]);
            float e3 = ex2f(s[nb][3]);
            lsum_lo += e0 + e1;
            lsum_hi += e2 + e3;
            *(float2*)&pw[nb * 8]           = make_float2(e0, e1);
            *(float2*)&pw[8 * PP + nb * 8]  = make_float2(e2, e3);
        }
        __syncwarp();

        // ---- O += P @ V : warp tile 16 x 256, K=32 (P is warp-private)
        uint32_t paf[4][4];
        #pragma unroll
        for (int ks = 0; ks < 4; ks++) {
            paf[ks][0] = f2u(pa[ks * 8]);
            paf[ks][1] = f2u(pa[8 * PP + ks * 8]);
            paf[ks][2] = f2u(pa[ks * 8 + 4]);
            paf[ks][3] = f2u(pa[8 * PP + ks * 8 + 4]);
        }
        #pragma unroll 8
        for (int nb = 0; nb < 32; nb++) {
            #pragma unroll
            for (int ks = 0; ks < 4; ks++) {
                uint32_t b0 = f2u(vb[ks * 8 * VP + nb * 8]);
                uint32_t b1 = f2u(vb[(ks * 8 + 4) * VP + nb * 8]);
                mma_tf32(Oacc[nb], paf[ks][0], paf[ks][1], paf[ks][2], paf[ks][3], b0, b1);
            }
        }
    }

    // ---- row-sum reduce across the 4 col-group lanes
    lsum_lo += __shfl_xor_sync(0xffffffffu, lsum_lo, 1);
    lsum_lo += __shfl_xor_sync(0xffffffffu, lsum_lo, 2);
    lsum_hi += __shfl_xor_sync(0xffffffffu, lsum_hi, 1);
    lsum_hi += __shfl_xor_sync(0xffffffffu, lsum_hi, 2);
    float inv_lo = 1.f / lsum_lo;
    float inv_hi = 1.f / lsum_hi;

    // ---- normalize, stage transposed [ch][row], store channel-major
    __syncthreads();      // everyone done reading Qs before aliasing as Os
    #pragma unroll
    for (int nb = 0; nb < 32; nb++) {
        int c0 = nb * 8 + 2 * t;
        Os[(c0 + 0) * 129 + wrow + g]     = Oacc[nb][0] * inv_lo;
        Os[(c0 + 1) * 129 + wrow + g]     = Oacc[nb][1] * inv_lo;
        Os[(c0 + 0) * 129 + wrow + g + 8] = Oacc[nb][2] * inv_hi;
        Os[(c0 + 1) * 129 + wrow + g + 8] = Oacc[nb][3] * inv_hi;
    }
    __syncthreads();
    float* ab = g_attn + (size_t)b * C_ * N_;
    for (int idx = tid; idx < 32768; idx += 256) {
        int c = idx >> 7, r = idx & 127;
        ab[(size_t)c * N_ + n0 + r] = Os[c * 129 + r];
    }
}

// ---------------------------------------------------------------------------
// Kernel 4: output projection + bias + residual
// ---------------------------------------------------------------------------
__global__ __launch_bounds__(256) void out_proj_kernel(
    const float* __restrict__ w,
    const float* __restrict__ bias,
    const float* __restrict__ x,
    float* __restrict__ out)
{
    __shared__ float Ws[16][65];
    __shared__ float Xs[16][64];
    int n0 = blockIdx.x * 64;
    int o0 = blockIdx.y * 64;
    int b  = blockIdx.z;
    int tid = threadIdx.x;
    int tx = tid & 15, ty = tid >> 4;
    const float* ab = g_attn + (size_t)b * C_ * N_;
    float acc[4][4] = {};
    int wc = tid & 15, wo = tid >> 4;
    int xn = tid & 63, xc = tid >> 6;

    for (int cb = 0; cb < C_; cb += 16) {
        #pragma unroll
        for (int oo = 0; oo < 64; oo += 16)
            Ws[wc][wo + oo] = w[(size_t)(o0 + wo + oo) * C_ + cb + wc];
        #pragma unroll
        for (int cc = 0; cc < 16; cc += 4) {
            int c = cb + xc + cc;
            Xs[xc + cc][xn] = ab[(size_t)c * N_ + n0 + xn];
        }
        __syncthreads();
        #pragma unroll
        for (int kk = 0; kk < 16; kk++) {
            float4 xv = *(const float4*)&Xs[kk][4 * tx];
            float w0 = Ws[kk][4 * ty + 0];
            float w1 = Ws[kk][4 * ty + 1];
            float w2 = Ws[kk][4 * ty + 2];
            float w3 = Ws[kk][4 * ty + 3];
            acc[0][0] += w0 * xv.x; acc[0][1] += w0 * xv.y; acc[0][2] += w0 * xv.z; acc[0][3] += w0 * xv.w;
            acc[1][0] += w1 * xv.x; acc[1][1] += w1 * xv.y; acc[1][2] += w1 * xv.z; acc[1][3] += w1 * xv.w;
            acc[2][0] += w2 * xv.x; acc[2][1] += w2 * xv.y; acc[2][2] += w2 * xv.z; acc[2][3] += w2 * xv.w;
            acc[3][0] += w3 * xv.x; acc[3][1] += w3 * xv.y; acc[3][2] += w3 * xv.z; acc[3][3] += w3 * xv.w;
        }
        __syncthreads();
    }
    #pragma unroll
    for (int i = 0; i < 4; i++) {
        int o = o0 + 4 * ty + i;
        float bo = bias[o];
        size_t base = ((size_t)b * C_ + o) * N_ + n0 + 4 * tx;
        float4 res = *(const float4*)&x[base];
        float4 r = make_float4(acc[i][0] + bo + res.x,
                               acc[i][1] + bo + res.y,
                               acc[i][2] + bo + res.z,
                               acc[i][3] + bo + res.w);
        *(float4*)&out[base] = r;
    }
}

// ---------------------------------------------------------------------------
// Launch
// ---------------------------------------------------------------------------
extern "C" void kernel_launch(void* const* d_in, const int* in_sizes, int n_in,
                              void* d_out, int out_size)
{
    const float* x        = (const float*)d_in[0];
    const float* gn_scale = (const float*)d_in[1];
    const float* gn_bias  = (const float*)d_in[2];
    const float* w_qkv    = (const float*)d_in[3];
    const float* b_qkv    = (const float*)d_in[4];
    const float* w_out    = (const float*)d_in[5];
    const float* b_out    = (const float*)d_in[6];
    float* out = (float*)d_out;

    cudaFuncSetAttribute(flash_kernel,
                         cudaFuncAttributeMaxDynamicSharedMemorySize, FL_SMEM);

    gn_stats_kernel<<<B_ * G_, 256>>>(x, gn_scale, gn_bias);
    qkv_gemm_kernel<<<dim3(N_ / 64, 12, B_), 256>>>(x, w_qkv, b_qkv);
    flash_kernel<<<dim3(N_ / 128, B_), 256, FL_SMEM>>>();
    out_proj_kernel<<<dim3(N_ / 64, 4, B_), 256>>>(w_out, b_out, x, out);
}

// round 7
// speedup vs baseline: 3.6576x; 1.4244x over previous
#include <cuda_runtime.h>
#include <cuda_fp16.h>
#include <cstdint>

// ---------------------------------------------------------------------------
// Problem constants
// ---------------------------------------------------------------------------
#define B_   8
#define C_   256
#define N_   4096
#define G_   8
#define CPG_ 32
#define EPS_ 1e-5f
// log2(e) / sqrt(C) folded into Q (stored pre-scaled) so P = exp2(S)
#define QSCALE_ 0.09016844270216718f

// ---------------------------------------------------------------------------
// Device scratch
// ---------------------------------------------------------------------------
__device__ __half g_qh[(size_t)B_ * N_ * C_];   // (B, N, C) token-major, pre-scaled
__device__ __half g_kh[(size_t)B_ * N_ * C_];   // (B, N, C) token-major
__device__ __half g_vh[(size_t)B_ * C_ * N_];   // (B, C, N) channel-major
__device__ float  g_attn[(size_t)B_ * C_ * N_]; // (B, C, N) float
__device__ float  g_fs[B_ * C_];
__device__ float  g_fb[B_ * C_];

// ---------------------------------------------------------------------------
// Helpers
// ---------------------------------------------------------------------------
__device__ __forceinline__ void mma_f16(float* c,
    uint32_t a0, uint32_t a1, uint32_t a2, uint32_t a3,
    uint32_t b0, uint32_t b1)
{
    asm volatile(
        "mma.sync.aligned.m16n8k16.row.col.f32.f16.f16.f32 "
        "{%0,%1,%2,%3}, {%4,%5,%6,%7}, {%8,%9}, {%0,%1,%2,%3};"
        : "+f"(c[0]), "+f"(c[1]), "+f"(c[2]), "+f"(c[3])
        : "r"(a0), "r"(a1), "r"(a2), "r"(a3), "r"(b0), "r"(b1));
}
__device__ __forceinline__ float ex2f(float x) {
    float r;
    asm("ex2.approx.ftz.f32 %0, %1;" : "=f"(r) : "f"(x));
    return r;
}
__device__ __forceinline__ uint32_t fp2h2(float lo, float hi) {
    __half2 h = __floats2half2_rn(lo, hi);
    return *reinterpret_cast<uint32_t*>(&h);
}
__device__ __forceinline__ uint32_t ldh2(const __half* p) {
    return *reinterpret_cast<const uint32_t*>(p);
}

// ---------------------------------------------------------------------------
// Kernel 1: GroupNorm stats -> fused per-(b,c) scale/bias
// ---------------------------------------------------------------------------
__global__ __launch_bounds__(256) void gn_stats_kernel(
    const float* __restrict__ x,
    const float* __restrict__ gamma,
    const float* __restrict__ beta)
{
    int b = blockIdx.x >> 3;
    int g = blockIdx.x & 7;
    const float4* p = reinterpret_cast<const float4*>(
        x + ((size_t)(b * C_ + g * CPG_)) * N_);
    float s1 = 0.f, s2 = 0.f;
    for (int i = threadIdx.x; i < 32768; i += 256) {
        float4 v = p[i];
        s1 += (v.x + v.y) + (v.z + v.w);
        s2 += (v.x * v.x + v.y * v.y) + (v.z * v.z + v.w * v.w);
    }
    #pragma unroll
    for (int off = 16; off; off >>= 1) {
        s1 += __shfl_xor_sync(0xffffffffu, s1, off);
        s2 += __shfl_xor_sync(0xffffffffu, s2, off);
    }
    __shared__ float a1[8], a2[8];
    __shared__ float sh_mean, sh_rstd;
    int warp = threadIdx.x >> 5;
    if ((threadIdx.x & 31) == 0) { a1[warp] = s1; a2[warp] = s2; }
    __syncthreads();
    if (threadIdx.x == 0) {
        float t1 = 0.f, t2 = 0.f;
        #pragma unroll
        for (int w = 0; w < 8; w++) { t1 += a1[w]; t2 += a2[w]; }
        float mean = t1 * (1.f / 131072.f);
        float var  = t2 * (1.f / 131072.f) - mean * mean;
        sh_mean = mean;
        sh_rstd = rsqrtf(var + EPS_);
    }
    __syncthreads();
    if (threadIdx.x < CPG_) {
        int c  = g * CPG_ + threadIdx.x;
        float ga = gamma[c];
        float fs = sh_rstd * ga;
        g_fs[b * C_ + c] = fs;
        g_fb[b * C_ + c] = beta[c] - sh_mean * fs;
    }
}

// ---------------------------------------------------------------------------
// Kernel 2: QKV GEMM (fused GN). Outputs fp16:
//   Q (token-major, pre-scaled by QSCALE), K (token-major), V (channel-major).
// ---------------------------------------------------------------------------
#define TSP 68
__global__ __launch_bounds__(256) void qkv_gemm_kernel(
    const float* __restrict__ x,
    const float* __restrict__ w,
    const float* __restrict__ bias)
{
    __shared__ float Ws[16][65];
    __shared__ float Xs[16][64];
    __shared__ float Ts[64][TSP];
    int n0 = blockIdx.x * 64;
    int o0 = blockIdx.y * 64;
    int b  = blockIdx.z;
    int tid = threadIdx.x;
    int tx = tid & 15, ty = tid >> 4;
    const float* xb  = x + (size_t)b * C_ * N_;
    const float* fsb = g_fs + b * C_;
    const float* fbb = g_fb + b * C_;
    float acc[4][4] = {};
    int wc = tid & 15, wo = tid >> 4;
    int xn = tid & 63, xc = tid >> 6;

    for (int cb = 0; cb < C_; cb += 16) {
        #pragma unroll
        for (int oo = 0; oo < 64; oo += 16)
            Ws[wc][wo + oo] = w[(size_t)(o0 + wo + oo) * C_ + cb + wc];
        #pragma unroll
        for (int cc = 0; cc < 16; cc += 4) {
            int c = cb + xc + cc;
            Xs[xc + cc][xn] = xb[(size_t)c * N_ + n0 + xn] * fsb[c] + fbb[c];
        }
        __syncthreads();
        #pragma unroll
        for (int kk = 0; kk < 16; kk++) {
            float4 xv = *(const float4*)&Xs[kk][4 * tx];
            float w0 = Ws[kk][4 * ty + 0];
            float w1 = Ws[kk][4 * ty + 1];
            float w2 = Ws[kk][4 * ty + 2];
            float w3 = Ws[kk][4 * ty + 3];
            acc[0][0] += w0 * xv.x; acc[0][1] += w0 * xv.y; acc[0][2] += w0 * xv.z; acc[0][3] += w0 * xv.w;
            acc[1][0] += w1 * xv.x; acc[1][1] += w1 * xv.y; acc[1][2] += w1 * xv.z; acc[1][3] += w1 * xv.w;
            acc[2][0] += w2 * xv.x; acc[2][1] += w2 * xv.y; acc[2][2] += w2 * xv.z; acc[2][3] += w2 * xv.w;
            acc[3][0] += w3 * xv.x; acc[3][1] += w3 * xv.y; acc[3][2] += w3 * xv.z; acc[3][3] += w3 * xv.w;
        }
        __syncthreads();
    }

    int t = o0 >> 8;          // 0 = Q, 1 = K, 2 = V
    if (t < 2) {
        // stage (transpose) then write token-major [n][c] as half
        #pragma unroll
        for (int i = 0; i < 4; i++) {
            float bo = bias[o0 + 4 * ty + i];
            #pragma unroll
            for (int j = 0; j < 4; j++)
                Ts[4 * tx + j][4 * ty + i] = acc[i][j] + bo;
        }
        __syncthreads();
        __half* gdst = (t == 0 ? g_qh : g_kh) + (size_t)b * N_ * C_;
        float scale = (t == 0) ? QSCALE_ : 1.f;
        int oo0 = o0 & 255;
        int r = tid >> 2, cq = (tid & 3) * 16;
        __half* drow = gdst + (size_t)(n0 + r) * C_ + oo0 + cq;
        uint32_t outw[8];
        #pragma unroll
        for (int j = 0; j < 8; j++)
            outw[j] = fp2h2(Ts[r][cq + 2 * j] * scale, Ts[r][cq + 2 * j + 1] * scale);
        *(uint4*)(drow)     = make_uint4(outw[0], outw[1], outw[2], outw[3]);
        *(uint4*)(drow + 8) = make_uint4(outw[4], outw[5], outw[6], outw[7]);
    } else {
        // V: channel-major half, direct
        #pragma unroll
        for (int i = 0; i < 4; i++) {
            int o = o0 + 4 * ty + i;
            float bo = bias[o];
            uint2 val = make_uint2(fp2h2(acc[i][0] + bo, acc[i][1] + bo),
                                   fp2h2(acc[i][2] + bo, acc[i][3] + bo));
            *(uint2*)&g_vh[((size_t)b * C_ + (o & 255)) * N_ + n0 + 4 * tx] = val;
        }
    }
}

// ---------------------------------------------------------------------------
// Kernel 3: flash attention on mma.sync f16 (m16n8k16), fp32 accum.
// 256 threads / 8 warps; warp = 16 query rows -> 128 rows/CTA; key blocks 32.
// No max-subtraction softmax (bounded scores); O accumulates in registers.
// Half strides: QP=KP=264 (132w: bank 4g+t), VP=PP=40 (20w pattern) -- all
// fragment half2 accesses hit 32 distinct banks.
// ---------------------------------------------------------------------------
#define QPH 264
#define KPH 264
#define VPH 40
#define PPH 40
#define QWH (128 * QPH)                 // 33792 halves
#define KWH (32 * KPH)                  // 8448
#define VWH (256 * VPH)                 // 10240
#define PWH (128 * PPH)                 // 5120
#define FL_SMEM ((QWH + KWH + VWH + PWH) * 2)   // 115200 bytes

__global__ void __launch_bounds__(256, 1) flash_kernel()
{
    extern __shared__ __align__(16) char smraw[];
    __half* Qh = (__half*)smraw;
    __half* Kh = Qh + QWH;
    __half* Vh = Kh + KWH;
    __half* Ph = Vh + VWH;
    float*  Os = (float*)smraw;         // epilogue alias (128*129 floats)

    int tid = threadIdx.x;
    int w   = tid >> 5;
    int lid = tid & 31;
    int g   = lid >> 2;                 // fragment row group 0..7
    int t   = lid & 3;                  // fragment col group 0..3
    int b   = blockIdx.y;
    int n0  = blockIdx.x * 128;
    int wrow = w * 16;

    const __half* qg = g_qh + ((size_t)b * N_ + n0) * C_;
    const __half* kg = g_kh + (size_t)b * N_ * C_;
    const __half* vg = g_vh + (size_t)b * C_ * N_;

    // ---- Q fill: 128 rows x 256 halves (pre-scaled in qkv kernel)
    for (int idx = tid; idx < 4096; idx += 256) {
        int r = idx >> 5, c8 = idx & 31;
        *(uint4*)(Qh + r * QPH + c8 * 8) =
            *(const uint4*)(qg + (size_t)r * C_ + c8 * 8);
    }

    const __half* qrow = Qh + (wrow + g) * QPH + 2 * t;
    const __half* krow = Kh + g * KPH + 2 * t;
    __half*       prow = Ph + (wrow + g) * PPH + 2 * t;

    float Oacc[32][4];
    #pragma unroll
    for (int nb = 0; nb < 32; nb++)
        #pragma unroll
        for (int j = 0; j < 4; j++) Oacc[nb][j] = 0.f;
    float lsum_lo = 0.f, lsum_hi = 0.f;

    for (int i = 0; i < 128; i++) {
        __syncthreads();
        // K tile: 32 keys x 256 halves (token-major)
        for (int idx = tid; idx < 1024; idx += 256) {
            int r = idx >> 5, c8 = idx & 31;
            *(uint4*)(Kh + r * KPH + c8 * 8) =
                *(const uint4*)(kg + (size_t)(i * 32 + r) * C_ + c8 * 8);
        }
        // V tile: 256 channels x 32 halves (channel-major)
        for (int idx = tid; idx < 1024; idx += 256) {
            int c = idx >> 2, q = idx & 3;
            *(uint4*)(Vh + c * VPH + q * 8) =
                *(const uint4*)(vg + (size_t)c * N_ + i * 32 + q * 8);
        }
        __syncthreads();

        // ---- S = Q @ K^T : warp tile 16 x 32, K=256 (16 k-steps of 16)
        float s[4][4];
        #pragma unroll
        for (int nb = 0; nb < 4; nb++)
            #pragma unroll
            for (int j = 0; j < 4; j++) s[nb][j] = 0.f;
        #pragma unroll 4
        for (int kk = 0; kk < 16; kk++) {
            uint32_t a0 = ldh2(qrow + kk * 16);
            uint32_t a1 = ldh2(qrow + 8 * QPH + kk * 16);
            uint32_t a2 = ldh2(qrow + kk * 16 + 8);
            uint32_t a3 = ldh2(qrow + 8 * QPH + kk * 16 + 8);
            #pragma unroll
            for (int nb = 0; nb < 4; nb++) {
                uint32_t b0 = ldh2(krow + nb * 8 * KPH + kk * 16);
                uint32_t b1 = ldh2(krow + nb * 8 * KPH + kk * 16 + 8);
                mma_f16(s[nb], a0, a1, a2, a3, b0, b1);
            }
        }

        // ---- P = exp2(S) (half), accumulate row sums in fp32
        #pragma unroll
        for (int nb = 0; nb < 4; nb++) {
            float e0 = ex2f(s[nb][0]);
            float e1 = ex2f(s[nb][1]);
            float e2 = ex2f(s[nb][2]);
            float e3 = ex2f(s[nb][3]);
            lsum_lo += e0 + e1;
            lsum_hi += e2 + e3;
            *(uint32_t*)(prow + nb * 8)           = fp2h2(e0, e1);
            *(uint32_t*)(prow + 8 * PPH + nb * 8) = fp2h2(e2, e3);
        }
        __syncwarp();

        // ---- O += P @ V : warp tile 16 x 256, K=32 (2 k-steps of 16)
        uint32_t pa[2][4];
        #pragma unroll
        for (int k2 = 0; k2 < 2; k2++) {
            pa[k2][0] = ldh2(prow + k2 * 16);
            pa[k2][1] = ldh2(prow + 8 * PPH + k2 * 16);
            pa[k2][2] = ldh2(prow + k2 * 16 + 8);
            pa[k2][3] = ldh2(prow + 8 * PPH + k2 * 16 + 8);
        }
        #pragma unroll 8
        for (int nb = 0; nb < 32; nb++) {
            const __half* vb = Vh + (nb * 8 + g) * VPH + 2 * t;
            uint32_t b0 = ldh2(vb);
            uint32_t b1 = ldh2(vb + 8);
            mma_f16(Oacc[nb], pa[0][0], pa[0][1], pa[0][2], pa[0][3], b0, b1);
            b0 = ldh2(vb + 16);
            b1 = ldh2(vb + 24);
            mma_f16(Oacc[nb], pa[1][0], pa[1][1], pa[1][2], pa[1][3], b0, b1);
        }
    }

    // ---- row-sum reduce across the 4 col-group lanes
    lsum_lo += __shfl_xor_sync(0xffffffffu, lsum_lo, 1);
    lsum_lo += __shfl_xor_sync(0xffffffffu, lsum_lo, 2);
    lsum_hi += __shfl_xor_sync(0xffffffffu, lsum_hi, 1);
    lsum_hi += __shfl_xor_sync(0xffffffffu, lsum_hi, 2);
    float inv_lo = 1.f / lsum_lo;
    float inv_hi = 1.f / lsum_hi;

    // ---- normalize + transpose through smem in 2 chunks of 128 channels
    float* ab = g_attn + (size_t)b * C_ * N_;
    #pragma unroll
    for (int h = 0; h < 2; h++) {
        __syncthreads();
        #pragma unroll
        for (int nb = 0; nb < 16; nb++) {
            int nbg = h * 16 + nb;
            int c0 = nb * 8 + 2 * t;
            Os[(c0 + 0) * 129 + wrow + g]     = Oacc[nbg][0] * inv_lo;
            Os[(c0 + 1) * 129 + wrow + g]     = Oacc[nbg][1] * inv_lo;
            Os[(c0 + 0) * 129 + wrow + g + 8] = Oacc[nbg][2] * inv_hi;
            Os[(c0 + 1) * 129 + wrow + g + 8] = Oacc[nbg][3] * inv_hi;
        }
        __syncthreads();
        for (int idx = tid; idx < 16384; idx += 256) {
            int c = idx >> 7, r = idx & 127;
            ab[(size_t)(h * 128 + c) * N_ + n0 + r] = Os[c * 129 + r];
        }
    }
}

// ---------------------------------------------------------------------------
// Kernel 4: output projection + bias + residual
// ---------------------------------------------------------------------------
__global__ __launch_bounds__(256) void out_proj_kernel(
    const float* __restrict__ w,
    const float* __restrict__ bias,
    const float* __restrict__ x,
    float* __restrict__ out)
{
    __shared__ float Ws[16][65];
    __shared__ float Xs[16][64];
    int n0 = blockIdx.x * 64;
    int o0 = blockIdx.y * 64;
    int b  = blockIdx.z;
    int tid = threadIdx.x;
    int tx = tid & 15, ty = tid >> 4;
    const float* ab = g_attn + (size_t)b * C_ * N_;
    float acc[4][4] = {};
    int wc = tid & 15, wo = tid >> 4;
    int xn = tid & 63, xc = tid >> 6;

    for (int cb = 0; cb < C_; cb += 16) {
        #pragma unroll
        for (int oo = 0; oo < 64; oo += 16)
            Ws[wc][wo + oo] = w[(size_t)(o0 + wo + oo) * C_ + cb + wc];
        #pragma unroll
        for (int cc = 0; cc < 16; cc += 4) {
            int c = cb + xc + cc;
            Xs[xc + cc][xn] = ab[(size_t)c * N_ + n0 + xn];
        }
        __syncthreads();
        #pragma unroll
        for (int kk = 0; kk < 16; kk++) {
            float4 xv = *(const float4*)&Xs[kk][4 * tx];
            float w0 = Ws[kk][4 * ty + 0];
            float w1 = Ws[kk][4 * ty + 1];
            float w2 = Ws[kk][4 * ty + 2];
            float w3 = Ws[kk][4 * ty + 3];
            acc[0][0] += w0 * xv.x; acc[0][1] += w0 * xv.y; acc[0][2] += w0 * xv.z; acc[0][3] += w0 * xv.w;
            acc[1][0] += w1 * xv.x; acc[1][1] += w1 * xv.y; acc[1][2] += w1 * xv.z; acc[1][3] += w1 * xv.w;
            acc[2][0] += w2 * xv.x; acc[2][1] += w2 * xv.y; acc[2][2] += w2 * xv.z; acc[2][3] += w2 * xv.w;
            acc[3][0] += w3 * xv.x; acc[3][1] += w3 * xv.y; acc[3][2] += w3 * xv.z; acc[3][3] += w3 * xv.w;
        }
        __syncthreads();
    }
    #pragma unroll
    for (int i = 0; i < 4; i++) {
        int o = o0 + 4 * ty + i;
        float bo = bias[o];
        size_t base = ((size_t)b * C_ + o) * N_ + n0 + 4 * tx;
        float4 res = *(const float4*)&x[base];
        float4 r = make_float4(acc[i][0] + bo + res.x,
                               acc[i][1] + bo + res.y,
                               acc[i][2] + bo + res.z,
                               acc[i][3] + bo + res.w);
        *(float4*)&out[base] = r;
    }
}

// ---------------------------------------------------------------------------
// Launch
// ---------------------------------------------------------------------------
extern "C" void kernel_launch(void* const* d_in, const int* in_sizes, int n_in,
                              void* d_out, int out_size)
{
    const float* x        = (const float*)d_in[0];
    const float* gn_scale = (const float*)d_in[1];
    const float* gn_bias  = (const float*)d_in[2];
    const float* w_qkv    = (const float*)d_in[3];
    const float* b_qkv    = (const float*)d_in[4];
    const float* w_out    = (const float*)d_in[5];
    const float* b_out    = (const float*)d_in[6];
    float* out = (float*)d_out;

    cudaFuncSetAttribute(flash_kernel,
                         cudaFuncAttributeMaxDynamicSharedMemorySize, FL_SMEM);

    gn_stats_kernel<<<B_ * G_, 256>>>(x, gn_scale, gn_bias);
    qkv_gemm_kernel<<<dim3(N_ / 64, 12, B_), 256>>>(x, w_qkv, b_qkv);
    flash_kernel<<<dim3(N_ / 128, B_), 256, FL_SMEM>>>();
    out_proj_kernel<<<dim3(N_ / 64, 4, B_), 256>>>(w_out, b_out, x, out);
}

// round 8
// speedup vs baseline: 4.6540x; 1.2724x over previous
#include <cuda_runtime.h>
#include <cuda_fp16.h>
#include <cstdint>

// ---------------------------------------------------------------------------
// Problem constants
// ---------------------------------------------------------------------------
#define B_   8
#define C_   256
#define N_   4096
#define G_   8
#define CPG_ 32
#define EPS_ 1e-5f
#define QSCALE_ 0.09016844270216718f   // log2(e)/sqrt(C)

// ---------------------------------------------------------------------------
// Device scratch
// ---------------------------------------------------------------------------
__device__ __half g_xh[(size_t)B_ * N_ * C_];    // GN-applied x, token-major
__device__ __half g_qh[(size_t)B_ * N_ * C_];    // Q token-major, pre-scaled
__device__ __half g_kh[(size_t)B_ * N_ * C_];    // K token-major
__device__ __half g_vh[(size_t)B_ * C_ * N_];    // V channel-major
__device__ __half g_oh[(size_t)B_ * N_ * C_];    // attention out, token-major
__device__ __half g_wqh[3 * C_ * C_];            // w_qkv fp16 [o][c]
__device__ __half g_woh[C_ * C_];                // w_out fp16 [o][c]
__device__ float  g_fs[B_ * C_];
__device__ float  g_fb[B_ * C_];

// ---------------------------------------------------------------------------
// Helpers
// ---------------------------------------------------------------------------
__device__ __forceinline__ void mma_f16(float* c,
    uint32_t a0, uint32_t a1, uint32_t a2, uint32_t a3,
    uint32_t b0, uint32_t b1)
{
    asm volatile(
        "mma.sync.aligned.m16n8k16.row.col.f32.f16.f16.f32 "
        "{%0,%1,%2,%3}, {%4,%5,%6,%7}, {%8,%9}, {%0,%1,%2,%3};"
        : "+f"(c[0]), "+f"(c[1]), "+f"(c[2]), "+f"(c[3])
        : "r"(a0), "r"(a1), "r"(a2), "r"(a3), "r"(b0), "r"(b1));
}
__device__ __forceinline__ float ex2f(float x) {
    float r;
    asm("ex2.approx.ftz.f32 %0, %1;" : "=f"(r) : "f"(x));
    return r;
}
__device__ __forceinline__ uint32_t fp2h2(float lo, float hi) {
    __half2 h = __floats2half2_rn(lo, hi);
    return *reinterpret_cast<uint32_t*>(&h);
}
__device__ __forceinline__ uint32_t ldh2(const __half* p) {
    return *reinterpret_cast<const uint32_t*>(p);
}
__device__ __forceinline__ uint32_t smem_u32(const void* p) {
    uint32_t a;
    asm("{ .reg .u64 t; cvta.to.shared.u64 t, %1; cvt.u32.u64 %0, t; }"
        : "=r"(a) : "l"(p));
    return a;
}
__device__ __forceinline__ void cp16(uint32_t dst, const void* src) {
    asm volatile("cp.async.cg.shared.global [%0], [%1], 16;"
                 :: "r"(dst), "l"(src) : "memory");
}
#define CP_COMMIT() asm volatile("cp.async.commit_group;" ::: "memory")
#define CP_WAIT1()  asm volatile("cp.async.wait_group 1;" ::: "memory")
#define CP_WAIT0()  asm volatile("cp.async.wait_group 0;" ::: "memory")

// ---------------------------------------------------------------------------
// Kernel 1: GroupNorm stats -> fused per-(b,c) scale/bias
// ---------------------------------------------------------------------------
__global__ __launch_bounds__(256) void gn_stats_kernel(
    const float* __restrict__ x,
    const float* __restrict__ gamma,
    const float* __restrict__ beta)
{
    int b = blockIdx.x >> 3;
    int g = blockIdx.x & 7;
    const float4* p = reinterpret_cast<const float4*>(
        x + ((size_t)(b * C_ + g * CPG_)) * N_);
    float s1 = 0.f, s2 = 0.f;
    for (int i = threadIdx.x; i < 32768; i += 256) {
        float4 v = p[i];
        s1 += (v.x + v.y) + (v.z + v.w);
        s2 += (v.x * v.x + v.y * v.y) + (v.z * v.z + v.w * v.w);
    }
    #pragma unroll
    for (int off = 16; off; off >>= 1) {
        s1 += __shfl_xor_sync(0xffffffffu, s1, off);
        s2 += __shfl_xor_sync(0xffffffffu, s2, off);
    }
    __shared__ float a1[8], a2[8];
    __shared__ float sh_mean, sh_rstd;
    int warp = threadIdx.x >> 5;
    if ((threadIdx.x & 31) == 0) { a1[warp] = s1; a2[warp] = s2; }
    __syncthreads();
    if (threadIdx.x == 0) {
        float t1 = 0.f, t2 = 0.f;
        #pragma unroll
        for (int w = 0; w < 8; w++) { t1 += a1[w]; t2 += a2[w]; }
        float mean = t1 * (1.f / 131072.f);
        float var  = t2 * (1.f / 131072.f) - mean * mean;
        sh_mean = mean;
        sh_rstd = rsqrtf(var + EPS_);
    }
    __syncthreads();
    if (threadIdx.x < CPG_) {
        int c  = g * CPG_ + threadIdx.x;
        float ga = gamma[c];
        float fs = sh_rstd * ga;
        g_fs[b * C_ + c] = fs;
        g_fb[b * C_ + c] = beta[c] - sh_mean * fs;
    }
}

// ---------------------------------------------------------------------------
// Kernel 2a: weights fp32 -> fp16 (layout unchanged [o][c])
// ---------------------------------------------------------------------------
__global__ __launch_bounds__(256) void wconv_kernel(
    const float* __restrict__ wq, const float* __restrict__ wo)
{
    int i = blockIdx.x * 256 + threadIdx.x;      // 65536 threads
    for (int k = i; k < 3 * C_ * C_; k += 65536)
        g_wqh[k] = __float2half(wq[k]);
    if (i < C_ * C_)
        g_woh[i] = __float2half(wo[i]);
}

// ---------------------------------------------------------------------------
// Kernel 2b: xn = GN(x) as fp16 token-major (B, N, C)
// grid (N/256, C/64, B); per CTA: 4 sub-tiles of 64ch x 64tok transpose
// ---------------------------------------------------------------------------
__global__ __launch_bounds__(256) void xn_half_kernel(const float* __restrict__ x)
{
    __shared__ float T[64][65];
    int n0 = blockIdx.x * 256;
    int c0 = blockIdx.y * 64;
    int b  = blockIdx.z;
    int tid = threadIdx.x;
    const float* fsb = g_fs + b * C_;
    const float* fbb = g_fb + b * C_;

    for (int s = 0; s < 4; s++) {
        int nn0 = n0 + s * 64;
        for (int idx = tid; idx < 1024; idx += 256) {
            int cc = idx >> 4, nn4 = (idx & 15) * 4;
            float4 v = *(const float4*)&x[((size_t)(b * C_ + c0 + cc)) * N_ + nn0 + nn4];
            float fs = fsb[c0 + cc], fb = fbb[c0 + cc];
            T[cc][nn4 + 0] = v.x * fs + fb;
            T[cc][nn4 + 1] = v.y * fs + fb;
            T[cc][nn4 + 2] = v.z * fs + fb;
            T[cc][nn4 + 3] = v.w * fs + fb;
        }
        __syncthreads();
        for (int idx = tid; idx < 2048; idx += 256) {
            int nn = idx >> 5, c = (idx & 31) * 2;
            *(uint32_t*)&g_xh[((size_t)b * N_ + nn0 + nn) * C_ + c0 + c] =
                fp2h2(T[c][nn], T[c + 1][nn]);
        }
        __syncthreads();
    }
}

// ---------------------------------------------------------------------------
// Kernel 3: QKV GEMM on fp16 mma. CTA = 128 tokens x 128 outputs, K=256.
// grid (N/128, 6, B). Output chunk type: y>>1 = Q/K/V.
// ---------------------------------------------------------------------------
#define AP 264
#define HG_SMEM ((128 * AP + 128 * AP) * 2)   // 135168 B

__global__ __launch_bounds__(256) void qkv_hgemm_kernel(
    const float* __restrict__ bias)
{
    extern __shared__ __align__(16) char smraw[];
    __half* Ah = (__half*)smraw;
    __half* Bh = Ah + 128 * AP;

    int tid = threadIdx.x;
    int w = tid >> 5, lid = tid & 31;
    int g = lid >> 2, t = lid & 3;
    int wrow = w * 16;
    int n0 = blockIdx.x * 128;
    int o0 = blockIdx.y * 128;
    int b  = blockIdx.z;

    const __half* ag = g_xh + ((size_t)b * N_ + n0) * C_;
    const __half* bg = g_wqh + (size_t)o0 * C_;
    for (int idx = tid; idx < 4096; idx += 256) {
        int r = idx >> 5, c8 = idx & 31;
        *(uint4*)(Ah + r * AP + c8 * 8) = *(const uint4*)(ag + (size_t)r * C_ + c8 * 8);
        *(uint4*)(Bh + r * AP + c8 * 8) = *(const uint4*)(bg + (size_t)r * C_ + c8 * 8);
    }
    __syncthreads();

    const __half* ar = Ah + (wrow + g) * AP + 2 * t;
    const __half* br = Bh + g * AP + 2 * t;
    float acc[16][4];
    #pragma unroll
    for (int nb = 0; nb < 16; nb++)
        #pragma unroll
        for (int j = 0; j < 4; j++) acc[nb][j] = 0.f;

    #pragma unroll 4
    for (int kk = 0; kk < 16; kk++) {
        uint32_t a0 = ldh2(ar + kk * 16);
        uint32_t a1 = ldh2(ar + 8 * AP + kk * 16);
        uint32_t a2 = ldh2(ar + kk * 16 + 8);
        uint32_t a3 = ldh2(ar + 8 * AP + kk * 16 + 8);
        #pragma unroll
        for (int nb = 0; nb < 16; nb++) {
            uint32_t b0 = ldh2(br + nb * 8 * AP + kk * 16);
            uint32_t b1 = ldh2(br + nb * 8 * AP + kk * 16 + 8);
            mma_f16(acc[nb], a0, a1, a2, a3, b0, b1);
        }
    }

    // epilogue
    int type = blockIdx.y >> 1;           // 0 Q, 1 K, 2 V
    int n_lo = n0 + wrow + g;
    float scale = (type == 0) ? QSCALE_ : 1.f;
    #pragma unroll
    for (int nb = 0; nb < 16; nb++) {
        int og = o0 + nb * 8 + 2 * t;     // global output in [0,768)
        int oo = og & 255;
        float b0v = bias[og], b1v = bias[og + 1];
        float d0 = (acc[nb][0] + b0v) * scale;
        float d1 = (acc[nb][1] + b1v) * scale;
        float d2 = (acc[nb][2] + b0v) * scale;
        float d3 = (acc[nb][3] + b1v) * scale;
        if (type < 2) {
            __half* dst = (type == 0 ? g_qh : g_kh) + ((size_t)b * N_ + n_lo) * C_ + oo;
            *(uint32_t*)dst = fp2h2(d0, d1);
            *(uint32_t*)(dst + 8 * C_) = fp2h2(d2, d3);
        } else {
            __half* vd = g_vh + ((size_t)b * C_ + oo) * N_;
            vd[n_lo]            = __float2half(d0);
            vd[N_ + n_lo]       = __float2half(d1);
            vd[n_lo + 8]        = __float2half(d2);
            vd[N_ + n_lo + 8]   = __float2half(d3);
        }
    }
}

// ---------------------------------------------------------------------------
// Kernel 4: flash attention, fp16 mma, cp.async double-buffered K/V tiles.
// 256 threads / 8 warps; 128 query rows/CTA; 128 key blocks of 32.
// ---------------------------------------------------------------------------
#define QPH 264
#define KPH 264
#define VPH 40
#define PPH 40
#define QWH (128 * QPH)
#define KWH (32 * KPH)
#define VWH (256 * VPH)
#define PWH (128 * PPH)
#define FL_SMEM ((QWH + 2 * KWH + 2 * VWH + PWH) * 2)   // 152576 B

__global__ void __launch_bounds__(256, 1) flash_kernel()
{
    extern __shared__ __align__(16) char smraw[];
    __half* Qh  = (__half*)smraw;
    __half* Kb0 = Qh + QWH;
    __half* Kb1 = Kb0 + KWH;
    __half* Vb0 = Kb1 + KWH;
    __half* Vb1 = Vb0 + VWH;
    __half* Ph  = Vb1 + VWH;
    uint32_t sb = smem_u32(smraw);
    uint32_t ka[2] = { sb + QWH * 2, sb + (QWH + KWH) * 2 };
    uint32_t va[2] = { sb + (QWH + 2 * KWH) * 2, sb + (QWH + 2 * KWH + VWH) * 2 };

    int tid = threadIdx.x;
    int w   = tid >> 5;
    int lid = tid & 31;
    int g   = lid >> 2;
    int t   = lid & 3;
    int b   = blockIdx.y;
    int n0  = blockIdx.x * 128;
    int wrow = w * 16;

    const __half* qg = g_qh + ((size_t)b * N_ + n0) * C_;
    const __half* kg = g_kh + (size_t)b * N_ * C_;
    const __half* vg = g_vh + (size_t)b * C_ * N_;

    // cp.async fill coords (8 x 16B per thread per tile)
    int kr = tid >> 5, kc8 = tid & 31;          // K: rows kr,kr+8,+16,+24
    int vc = tid >> 2, vq = tid & 3;            // V: chans vc,+64,+128,+192

    // prologue: issue tile 0
    {
        #pragma unroll
        for (int rr = 0; rr < 32; rr += 8)
            cp16(ka[0] + ((kr + rr) * KPH + kc8 * 8) * 2,
                 kg + (size_t)(kr + rr) * C_ + kc8 * 8);
        #pragma unroll
        for (int cc = 0; cc < 256; cc += 64)
            cp16(va[0] + ((vc + cc) * VPH + vq * 8) * 2,
                 vg + (size_t)(vc + cc) * N_ + vq * 8);
        CP_COMMIT();
    }

    // Q fill (overlaps tile-0 arrival)
    for (int idx = tid; idx < 4096; idx += 256) {
        int r = idx >> 5, c8 = idx & 31;
        *(uint4*)(Qh + r * QPH + c8 * 8) =
            *(const uint4*)(qg + (size_t)r * C_ + c8 * 8);
    }

    const __half* qrow = Qh + (wrow + g) * QPH + 2 * t;
    const __half* kr0 = Kb0 + g * KPH + 2 * t;
    const __half* kr1 = Kb1 + g * KPH + 2 * t;
    __half* prow = Ph + (wrow + g) * PPH + 2 * t;

    float Oacc[32][4];
    #pragma unroll
    for (int nb = 0; nb < 32; nb++)
        #pragma unroll
        for (int j = 0; j < 4; j++) Oacc[nb][j] = 0.f;
    float lsum_lo = 0.f, lsum_hi = 0.f;

    for (int i = 0; i < 128; i++) {
        __syncthreads();                         // prev compute done; next buf free
        if (i < 127) {
            int j = i + 1, bf = j & 1;
            #pragma unroll
            for (int rr = 0; rr < 32; rr += 8)
                cp16(ka[bf] + ((kr + rr) * KPH + kc8 * 8) * 2,
                     kg + (size_t)(j * 32 + kr + rr) * C_ + kc8 * 8);
            #pragma unroll
            for (int cc = 0; cc < 256; cc += 64)
                cp16(va[bf] + ((vc + cc) * VPH + vq * 8) * 2,
                     vg + (size_t)(vc + cc) * N_ + j * 32 + vq * 8);
            CP_COMMIT();
            CP_WAIT1();
        } else {
            CP_WAIT0();
        }
        __syncthreads();

        const __half* krow = (i & 1) ? kr1 : kr0;
        const __half* Vbuf = (i & 1) ? Vb1 : Vb0;

        // S = Q @ K^T
        float s[4][4];
        #pragma unroll
        for (int nb = 0; nb < 4; nb++)
            #pragma unroll
            for (int j = 0; j < 4; j++) s[nb][j] = 0.f;
        #pragma unroll 4
        for (int kk = 0; kk < 16; kk++) {
            uint32_t a0 = ldh2(qrow + kk * 16);
            uint32_t a1 = ldh2(qrow + 8 * QPH + kk * 16);
            uint32_t a2 = ldh2(qrow + kk * 16 + 8);
            uint32_t a3 = ldh2(qrow + 8 * QPH + kk * 16 + 8);
            #pragma unroll
            for (int nb = 0; nb < 4; nb++) {
                uint32_t b0 = ldh2(krow + nb * 8 * KPH + kk * 16);
                uint32_t b1 = ldh2(krow + nb * 8 * KPH + kk * 16 + 8);
                mma_f16(s[nb], a0, a1, a2, a3, b0, b1);
            }
        }

        // P = exp2(S)
        #pragma unroll
        for (int nb = 0; nb < 4; nb++) {
            float e0 = ex2f(s[nb][0]);
            float e1 = ex2f(s[nb][1]);
            float e2 = ex2f(s[nb][2]);
            float e3 = ex2f(s[nb][3]);
            lsum_lo += e0 + e1;
            lsum_hi += e2 + e3;
            *(uint32_t*)(prow + nb * 8)           = fp2h2(e0, e1);
            *(uint32_t*)(prow + 8 * PPH + nb * 8) = fp2h2(e2, e3);
        }
        __syncwarp();

        // O += P @ V
        uint32_t pa[2][4];
        #pragma unroll
        for (int k2 = 0; k2 < 2; k2++) {
            pa[k2][0] = ldh2(prow + k2 * 16);
            pa[k2][1] = ldh2(prow + 8 * PPH + k2 * 16);
            pa[k2][2] = ldh2(prow + k2 * 16 + 8);
            pa[k2][3] = ldh2(prow + 8 * PPH + k2 * 16 + 8);
        }
        #pragma unroll 8
        for (int nb = 0; nb < 32; nb++) {
            const __half* vb = Vbuf + (nb * 8 + g) * VPH + 2 * t;
            uint32_t b0 = ldh2(vb);
            uint32_t b1 = ldh2(vb + 8);
            mma_f16(Oacc[nb], pa[0][0], pa[0][1], pa[0][2], pa[0][3], b0, b1);
            b0 = ldh2(vb + 16);
            b1 = ldh2(vb + 24);
            mma_f16(Oacc[nb], pa[1][0], pa[1][1], pa[1][2], pa[1][3], b0, b1);
        }
    }

    // row-sum reduce across 4 col-group lanes
    lsum_lo += __shfl_xor_sync(0xffffffffu, lsum_lo, 1);
    lsum_lo += __shfl_xor_sync(0xffffffffu, lsum_lo, 2);
    lsum_hi += __shfl_xor_sync(0xffffffffu, lsum_hi, 1);
    lsum_hi += __shfl_xor_sync(0xffffffffu, lsum_hi, 2);
    float inv_lo = 1.f / lsum_lo;
    float inv_hi = 1.f / lsum_hi;

    // epilogue: normalized fp16 O, token-major, direct half2 stores
    __half* od = g_oh + ((size_t)b * N_ + n0 + wrow + g) * C_;
    #pragma unroll
    for (int nb = 0; nb < 32; nb++) {
        int c = nb * 8 + 2 * t;
        *(uint32_t*)(od + c) = fp2h2(Oacc[nb][0] * inv_lo, Oacc[nb][1] * inv_lo);
        *(uint32_t*)(od + 8 * C_ + c) = fp2h2(Oacc[nb][2] * inv_hi, Oacc[nb][3] * inv_hi);
    }
}

// ---------------------------------------------------------------------------
// Kernel 5: output projection on fp16 mma + bias + residual (fp32 out).
// CTA = 128 tokens x 128 outputs; grid (N/128, 2, B).
// ---------------------------------------------------------------------------
__global__ __launch_bounds__(256) void proj_hgemm_kernel(
    const float* __restrict__ bias,
    const float* __restrict__ x,
    float* __restrict__ out)
{
    extern __shared__ __align__(16) char smraw[];
    __half* Ah = (__half*)smraw;
    __half* Bh = Ah + 128 * AP;
    float* Ts  = (float*)smraw;          // reused after compute: 128 x 136

    int tid = threadIdx.x;
    int w = tid >> 5, lid = tid & 31;
    int g = lid >> 2, t = lid & 3;
    int wrow = w * 16;
    int n0 = blockIdx.x * 128;
    int o0 = blockIdx.y * 128;
    int b  = blockIdx.z;

    const __half* ag = g_oh + ((size_t)b * N_ + n0) * C_;
    const __half* bg = g_woh + (size_t)o0 * C_;
    for (int idx = tid; idx < 4096; idx += 256) {
        int r = idx >> 5, c8 = idx & 31;
        *(uint4*)(Ah + r * AP + c8 * 8) = *(const uint4*)(ag + (size_t)r * C_ + c8 * 8);
        *(uint4*)(Bh + r * AP + c8 * 8) = *(const uint4*)(bg + (size_t)r * C_ + c8 * 8);
    }
    __syncthreads();

    const __half* ar = Ah + (wrow + g) * AP + 2 * t;
    const __half* br = Bh + g * AP + 2 * t;
    float acc[16][4];
    #pragma unroll
    for (int nb = 0; nb < 16; nb++)
        #pragma unroll
        for (int j = 0; j < 4; j++) acc[nb][j] = 0.f;

    #pragma unroll 4
    for (int kk = 0; kk < 16; kk++) {
        uint32_t a0 = ldh2(ar + kk * 16);
        uint32_t a1 = ldh2(ar + 8 * AP + kk * 16);
        uint32_t a2 = ldh2(ar + kk * 16 + 8);
        uint32_t a3 = ldh2(ar + 8 * AP + kk * 16 + 8);
        #pragma unroll
        for (int nb = 0; nb < 16; nb++) {
            uint32_t b0 = ldh2(br + nb * 8 * AP + kk * 16);
            uint32_t b1 = ldh2(br + nb * 8 * AP + kk * 16 + 8);
            mma_f16(acc[nb], a0, a1, a2, a3, b0, b1);
        }
    }

    // stage D transposed [o_local][token] in fp32
    __syncthreads();
    #pragma unroll
    for (int nb = 0; nb < 16; nb++) {
        int ol = nb * 8 + 2 * t;
        Ts[ol * 136 + wrow + g]           = acc[nb][0];
        Ts[(ol + 1) * 136 + wrow + g]     = acc[nb][1];
        Ts[ol * 136 + wrow + g + 8]       = acc[nb][2];
        Ts[(ol + 1) * 136 + wrow + g + 8] = acc[nb][3];
    }
    __syncthreads();

    // coalesced store: out = D + bias + residual
    for (int idx = tid; idx < 4096; idx += 256) {
        int o = idx >> 5, n4 = (idx & 31) * 4;
        int og = o0 + o;
        float bo = bias[og];
        size_t base = ((size_t)b * C_ + og) * N_ + n0 + n4;
        float4 res = *(const float4*)&x[base];
        float4 d   = *(const float4*)&Ts[o * 136 + n4];
        float4 r = make_float4(d.x + bo + res.x, d.y + bo + res.y,
                               d.z + bo + res.z, d.w + bo + res.w);
        *(float4*)&out[base] = r;
    }
}

// ---------------------------------------------------------------------------
// Launch
// ---------------------------------------------------------------------------
extern "C" void kernel_launch(void* const* d_in, const int* in_sizes, int n_in,
                              void* d_out, int out_size)
{
    const float* x        = (const float*)d_in[0];
    const float* gn_scale = (const float*)d_in[1];
    const float* gn_bias  = (const float*)d_in[2];
    const float* w_qkv    = (const float*)d_in[3];
    const float* b_qkv    = (const float*)d_in[4];
    const float* w_out    = (const float*)d_in[5];
    const float* b_out    = (const float*)d_in[6];
    float* out = (float*)d_out;

    cudaFuncSetAttribute(flash_kernel,
                         cudaFuncAttributeMaxDynamicSharedMemorySize, FL_SMEM);
    cudaFuncSetAttribute(qkv_hgemm_kernel,
                         cudaFuncAttributeMaxDynamicSharedMemorySize, HG_SMEM);
    cudaFuncSetAttribute(proj_hgemm_kernel,
                         cudaFuncAttributeMaxDynamicSharedMemorySize, HG_SMEM);

    wconv_kernel<<<256, 256>>>(w_qkv, w_out);
    gn_stats_kernel<<<B_ * G_, 256>>>(x, gn_scale, gn_bias);
    xn_half_kernel<<<dim3(N_ / 256, C_ / 64, B_), 256>>>(x);
    qkv_hgemm_kernel<<<dim3(N_ / 128, 6, B_), 256, HG_SMEM>>>(b_qkv);
    flash_kernel<<<dim3(N_ / 128, B_), 256, FL_SMEM>>>();
    proj_hgemm_kernel<<<dim3(N_ / 128, 2, B_), 256, HG_SMEM>>>(b_out, x, out);
}